// round 16
// baseline (speedup 1.0000x reference)
#include <cuda_runtime.h>

// out[b,c,h,w] = x[b,c,h,w] * (h%3 != 0) * (w%3 != 0)
//
// Unfold(k=2,stride=3,dil=2,pad=1)+fold(identical geometry) == elementwise 0/1
// coverage mask, separable in h,w. Rows h%3==0 are all-zero in the output.
//
// R16 = R8/R14 champion structure (live-first split; live: 4 plane-strided
// batched loads MLP=4; zero: pure stores) with L2 eviction-priority hints.
// sm_103a ptxas requires 256-bit ops for evict hints, so all accesses are
// float8 (R5 showed 128 vs 256-bit width is perf-neutral here):
//   ld.global.nc.L2::evict_last.v8.f32  — pin 88 MB input set in L2
//   st.global.L2::evict_first.v8.f32    — output never re-read, evict first
//
// Geometry: 32768 planes of 32x32 f32; row = 32 floats = 4 float8 (one 128B
// line). Live rows/plane: 21 (h=3k/2+1). Zero rows/plane: 11 (h=3k).

static constexpr int THREADS     = 256;
static constexpr int PLANES      = 64 * 512;                    // 32768
static constexpr int PQ          = PLANES / 4;                  // 8192 (plane chunk)
static constexpr int LIVE_F8     = PQ * 21 * 4;                 // 688,128 per chunk
static constexpr int ZERO_F8     = PLANES * 11 * 4;             // 1,441,792
static constexpr int LIVE_BLOCKS = LIVE_F8 / THREADS;           // 2688
static constexpr int ZERO_BLOCKS = ZERO_F8 / THREADS;           // 5632

__device__ __forceinline__ void ldg256_evict_last(float v[8], const float* p) {
    asm volatile("ld.global.nc.L2::evict_last.v8.f32 "
                 "{%0,%1,%2,%3,%4,%5,%6,%7}, [%8];"
                 : "=f"(v[0]), "=f"(v[1]), "=f"(v[2]), "=f"(v[3]),
                   "=f"(v[4]), "=f"(v[5]), "=f"(v[6]), "=f"(v[7])
                 : "l"(p));
}

__device__ __forceinline__ void stg256_evict_first(float* p, const float v[8]) {
    asm volatile("st.global.L2::evict_first.v8.f32 "
                 "[%0], {%1,%2,%3,%4,%5,%6,%7,%8};"
                 :: "l"(p),
                    "f"(v[0]), "f"(v[1]), "f"(v[2]), "f"(v[3]),
                    "f"(v[4]), "f"(v[5]), "f"(v[6]), "f"(v[7])
                 : "memory");
}

__device__ __forceinline__ void stg256_zero_evict_first(float* p) {
    asm volatile("st.global.L2::evict_first.v8.f32 "
                 "[%0], {%1,%1,%1,%1,%1,%1,%1,%1};"
                 :: "l"(p), "f"(0.0f) : "memory");
}

__global__ void __launch_bounds__(THREADS)
unfoldfold_split_kernel(const float* __restrict__ x,
                        float* __restrict__ out) {
    int b = blockIdx.x;

    if (b < LIVE_BLOCKS) {
        // ---- live rows: read (evict_last), mask by w, write (evict_first) ----
        int t = b * THREADS + threadIdx.x;      // [0, LIVE_F8)
        int c  = t & 3;                          // float8 column within row
        int r  = t >> 2;                         // live-row serial
        int k  = r % 21;                         // live-row index within plane
        int p0 = r / 21;                         // plane within first chunk
        int h  = (3 * k) / 2 + 1;                // 1,2,4,5,7,8,...,31

        int w0 = c << 3;                         // 0,8,16,24
        float m[8];
#pragma unroll
        for (int j = 0; j < 8; j++)
            m[j] = (float)(((w0 + j) % 3) != 0);

        size_t base = (size_t)h * 32 + (size_t)(c << 3);   // floats within plane
        const float* s0 = x + (size_t)(p0         ) * 1024 + base;
        const float* s1 = x + (size_t)(p0 +     PQ) * 1024 + base;
        const float* s2 = x + (size_t)(p0 + 2 * PQ) * 1024 + base;
        const float* s3 = x + (size_t)(p0 + 3 * PQ) * 1024 + base;

        float v0[8], v1[8], v2[8], v3[8];
        // Batched loads (MLP = 4), pinned in L2
        ldg256_evict_last(v0, s0);
        ldg256_evict_last(v1, s1);
        ldg256_evict_last(v2, s2);
        ldg256_evict_last(v3, s3);

#pragma unroll
        for (int j = 0; j < 8; j++) {
            v0[j] *= m[j]; v1[j] *= m[j]; v2[j] *= m[j]; v3[j] *= m[j];
        }

        float* d0 = out + (size_t)(p0         ) * 1024 + base;
        float* d1 = out + (size_t)(p0 +     PQ) * 1024 + base;
        float* d2 = out + (size_t)(p0 + 2 * PQ) * 1024 + base;
        float* d3 = out + (size_t)(p0 + 3 * PQ) * 1024 + base;

        stg256_evict_first(d0, v0);
        stg256_evict_first(d1, v1);
        stg256_evict_first(d2, v2);
        stg256_evict_first(d3, v3);
    } else {
        // ---- zero rows: pure 256-bit stores (evict_first), no loads ----
        int t = (b - LIVE_BLOCKS) * THREADS + threadIdx.x;   // [0, ZERO_F8)
        int c = t & 3;                           // float8 within row
        int r = t >> 2;                          // zero-row serial
        int k = r % 11;                          // zero-row index within plane
        int p = r / 11;
        int h = 3 * k;                           // 0,3,...,30

        stg256_zero_evict_first(out + (size_t)p * 1024 + h * 32 + (c << 3));
    }
}

extern "C" void kernel_launch(void* const* d_in, const int* in_sizes, int n_in,
                              void* d_out, int out_size) {
    const float* x = (const float*)d_in[0];
    float* out     = (float*)d_out;

    unfoldfold_split_kernel<<<LIVE_BLOCKS + ZERO_BLOCKS, THREADS>>>(x, out);
}

// round 17
// speedup vs baseline: 1.0485x; 1.0485x over previous
#include <cuda_runtime.h>

// out[b,c,h,w] = x[b,c,h,w] * (h%3 != 0) * (w%3 != 0)
//
// Unfold(k=2,stride=3,dil=2,pad=1)+fold(identical geometry) == elementwise 0/1
// coverage mask, separable in h,w: padded coordinate p is covered iff
// p = 3o + 2k (o in [0,11), k in {0,1}); the sets {3o} and {3o+2} are disjoint
// so coverage is 0/1; cropping (p = h+1) gives mask (h%3 != 0) * (w%3 != 0).
//
// FINAL champion (R8: ncu 27.3us, DRAM 75.3%, ~7.4 TB/s combined goodput):
//  - LIVE blocks first: rows h%3!=0. Unconditional LDG.128 x4 (plane-strided,
//    MLP=4), masked multiply, plain STG.128. Reads (the long-latency critical
//    path) start at cycle 0.
//  - ZERO blocks after: rows h%3==0. Pure STG.128 of zeros — no loads, no
//    scoreboard waits; they drain write bandwidth during the read tail.
//
// Measured and rejected: zero-first / interleaved ordering, MLP=8, fused
// zero-into-live, __stcs, L2 evict_last/evict_first hints, 256-bit width,
// persistent grid — all regressed or neutral.
//
// Geometry: 32768 planes of 32x32 f32; one plane = 256 float4; one row = 8
// float4 (one 128B line). Live rows/plane: 21 (h = 3k/2+1, k=0..20). Zero
// rows/plane: 11 (h = 3k, k=0..10).

static constexpr int THREADS     = 256;
static constexpr int PLANES      = 64 * 512;                    // 32768
static constexpr int PQ          = PLANES / 4;                  // 8192 (plane chunk)
static constexpr int LIVE_F4     = PQ * 21 * 8;                 // 1,376,256 per chunk
static constexpr int ZERO_F4     = PLANES * 11 * 8;             // 2,883,584
static constexpr int LIVE_BLOCKS = LIVE_F4 / THREADS;           // 5376
static constexpr int ZERO_BLOCKS = ZERO_F4 / THREADS;           // 11264

__global__ void __launch_bounds__(THREADS)
unfoldfold_split_kernel(const float4* __restrict__ x,
                        float4* __restrict__ out) {
    int b = blockIdx.x;

    if (b < LIVE_BLOCKS) {
        // ---- live rows: read, mask by w, write ----
        int t = b * THREADS + threadIdx.x;      // [0, LIVE_F4)
        int c  = t & 7;                          // float4 column within row
        int r  = t >> 3;                         // live-row serial
        int k  = r % 21;                         // live-row index within plane
        int p0 = r / 21;                         // plane within first chunk
        int h  = (3 * k) / 2 + 1;                // 1,2,4,5,7,8,...,31

        int w0 = c << 2;
        float m0 = (float)(((w0 + 0) % 3) != 0);
        float m1 = (float)(((w0 + 1) % 3) != 0);
        float m2 = (float)(((w0 + 2) % 3) != 0);
        float m3 = (float)(((w0 + 3) % 3) != 0);

        int base = h * 8 + c;                    // offset within a plane
        int i0 = (p0         ) * 256 + base;
        int i1 = (p0 +     PQ) * 256 + base;
        int i2 = (p0 + 2 * PQ) * 256 + base;
        int i3 = (p0 + 3 * PQ) * 256 + base;

        // Unconditional, batched loads (MLP = 4)
        float4 v0 = x[i0];
        float4 v1 = x[i1];
        float4 v2 = x[i2];
        float4 v3 = x[i3];

        v0.x *= m0; v0.y *= m1; v0.z *= m2; v0.w *= m3;
        v1.x *= m0; v1.y *= m1; v1.z *= m2; v1.w *= m3;
        v2.x *= m0; v2.y *= m1; v2.z *= m2; v2.w *= m3;
        v3.x *= m0; v3.y *= m1; v3.z *= m2; v3.w *= m3;

        out[i0] = v0;
        out[i1] = v1;
        out[i2] = v2;
        out[i3] = v3;
    } else {
        // ---- zero rows: pure stores, no loads, no waits ----
        int t = (b - LIVE_BLOCKS) * THREADS + threadIdx.x;   // [0, ZERO_F4)
        int c = t & 7;
        int r = t >> 3;
        int k = r % 11;                          // zero-row index within plane
        int p = r / 11;
        int h = 3 * k;                           // 0,3,...,30

        out[p * 256 + h * 8 + c] = make_float4(0.f, 0.f, 0.f, 0.f);
    }
}

extern "C" void kernel_launch(void* const* d_in, const int* in_sizes, int n_in,
                              void* d_out, int out_size) {
    const float4* x = (const float4*)d_in[0];
    float4* out     = (float4*)d_out;

    unfoldfold_split_kernel<<<LIVE_BLOCKS + ZERO_BLOCKS, THREADS>>>(x, out);
}